// round 6
// baseline (speedup 1.0000x reference)
#include <cuda_runtime.h>
#include <cuda_bf16.h>
#include <cstdint>

// ============================ problem constants ============================
#define NROWS   8192
#define BHALF   4096
#define DIM     256
#define INV_T   14.2857142857142857f      // 1/0.07
#define K2      20.609929155556620f        // log2(e)/0.07  (for ex2)

#define NCTA    148
#define NTILES  2080        // total 128x128 tile weight in the circulant triangle

// SMEM row: 256 bf16 + 8 pad = 528 B -> conflict-free ldmatrix + cp.async
#define ROW_B   528
#define TILEB   (128 * ROW_B)          // 67584 (one 128-row block)
#define OFF_A   2048                   // labs[2][256] ints at offset 0
#define OFF_B   (OFF_A + TILEB)        // 69632
#define SMEM_BYTES (OFF_B + 2 * TILEB) // 204800 (B holds up to 256 rows)

// ============================ device scratch ============================
__device__ __nv_bfloat16 g_Z[NROWS * DIM];   // normalized rows, bf16
__device__ int   g_lab[NROWS];
__device__ float g_pos[NROWS];
__device__ float g_se[NROWS];

// ============================ PTX helpers (baseline features only) ============================
__device__ __forceinline__ uint32_t smem_to_u32(const void* p) {
    uint32_t a;
    asm("{ .reg .u64 t; cvta.to.shared.u64 t, %1; cvt.u32.u64 %0, t; }" : "=r"(a) : "l"(p));
    return a;
}
__device__ __forceinline__ float ex2f(float x) {
    float y; asm("ex2.approx.f32 %0, %1;" : "=f"(y) : "f"(x)); return y;
}

#define LDSM_X4(r0, r1, r2, r3, addr) \
    asm volatile("ldmatrix.sync.aligned.m8n8.x4.shared.b16 {%0,%1,%2,%3}, [%4];" \
        : "=r"(r0), "=r"(r1), "=r"(r2), "=r"(r3) : "r"(addr))

#define MMA16816(c, a, b0, b1) \
    asm volatile("mma.sync.aligned.m16n8k16.row.col.f32.bf16.bf16.f32 " \
        "{%0,%1,%2,%3}, {%4,%5,%6,%7}, {%8,%9}, {%0,%1,%2,%3};" \
        : "+f"((c)[0]), "+f"((c)[1]), "+f"((c)[2]), "+f"((c)[3]) \
        : "r"((a)[0]), "r"((a)[1]), "r"((a)[2]), "r"((a)[3]), "r"(b0), "r"(b1))

#define CP_ASYNC16(dst_u32, src_ptr) \
    asm volatile("cp.async.cg.shared.global [%0], [%1], 16;" :: "r"(dst_u32), "l"(src_ptr))
#define CP_COMMIT() asm volatile("cp.async.commit_group;" ::: "memory")
#define CP_WAIT0()  asm volatile("cp.async.wait_group 0;" ::: "memory")

// ============================ circulant unit enumeration ============================
// ib < 32: units u=0 (diag, w=1), u=1..16 pairs (2u-1, 2u) covering d=1..32 (w=2 each)  -> 33
// ib >= 32: u=0 diag, u=1..15 pairs d=1..30, u=16 single d=31 (w=1)                     -> 32
__device__ __forceinline__ int unit_base(int i) { return (i < 32) ? 33 * i : 1056 + 32 * (i - 32); }
#define UNIT_TYPE(ibx, ux) ((ux) == 0 ? 0 : (((ibx) >= 32 && (ux) == 16) ? 1 : 2))  // 0 diag, 1 single, 2 pair

// ============================ kernel 1: normalize + bf16 + labels + init ============================
__global__ void k_norm(const float* __restrict__ zi, const float* __restrict__ zj,
                       const int* __restrict__ lab32, float* __restrict__ out) {
    __shared__ int stride_sh;
    if (threadIdx.x == 0) {
        int ored = 0;
#pragma unroll
        for (int i = 0; i < 32; i++) ored |= lab32[2 * i + 1];
        stride_sh = (ored == 0) ? 2 : 1;   // int64 storage has all-zero odd words (labels < 1000)
        if (blockIdx.x == 0) out[0] = 0.f;
    }
    int row  = blockIdx.x * 8 + (threadIdx.x >> 5);
    int lane = threadIdx.x & 31;
    const float* src = (row < BHALF) ? (zi + (size_t)row * DIM)
                                     : (zj + (size_t)(row - BHALF) * DIM);
    float v[8];
    float ss = 0.f;
#pragma unroll
    for (int i = 0; i < 8; i++) { v[i] = src[i * 32 + lane]; ss += v[i] * v[i]; }
#pragma unroll
    for (int o = 16; o > 0; o >>= 1) ss += __shfl_xor_sync(0xffffffffu, ss, o);
    float inv = 1.f / fmaxf(sqrtf(ss), 1e-12f);
    __nv_bfloat16* dst = g_Z + (size_t)row * DIM;
#pragma unroll
    for (int i = 0; i < 8; i++) dst[i * 32 + lane] = __float2bfloat16(v[i] * inv);
    __syncthreads();
    if (lane == 0) {
        g_lab[row] = lab32[(row & (BHALF - 1)) * stride_sh];
        g_pos[row] = 0.f;
        g_se[row]  = 0.f;
    }
}

// ============================ kernel 2: symmetric GEMM, persistent weighted CTAs ============================
__device__ __forceinline__ void cpasync_tile128(uint32_t dst, const __nv_bfloat16* src, int tid) {
#pragma unroll
    for (int it = 0; it < 8; it++) {
        int idx = tid + it * 512;        // 0..4095 16B-chunks
        int row = idx >> 5, c = idx & 31;
        const char* s = reinterpret_cast<const char*>(src) + row * 512 + c * 16;
        CP_ASYNC16(dst + row * ROW_B + c * 16, s);
    }
}

__global__ void __launch_bounds__(512, 1) k_sim() {
    extern __shared__ char smem[];
    uint32_t su = smem_to_u32(smem);
    int* labs = reinterpret_cast<int*>(smem);       // [2][256]
    const uint32_t offA = su + OFF_A;
    const uint32_t offB = su + OFF_B;

    int tid  = threadIdx.x;
    int lane = tid & 31;
    int wid  = tid >> 5;                 // 0..15
    const int wm  = (wid >> 2) * 32;     // m band
    const int wnN = (wid & 3) * 32;      // n band, narrow (128-wide unit)
    const int wnW = (wid & 3) * 64;      // n band, wide (256-wide unit)
    const int g   = lane >> 2;
    const int t4  = lane & 3;

    // ---- weighted unit range for this CTA ----
    int w0 = (blockIdx.x * NTILES) / NCTA;
    int w1 = ((blockIdx.x + 1) * NTILES) / NCTA;
    int ib, local;
    if (w0 < 1056) { ib = w0 / 33; local = w0 - 33 * ib; }
    else           { int x = w0 - 1056; ib = 32 + (x >> 5); local = x & 31; }
    int u = (local == 0) ? 0 : ((local - 1) >> 1) + 1;
    if (u > 0 && (2 * u - 1) < local) { u++; if (u > 16) { ib++; u = 0; } }
    if (ib >= 64 || unit_base(ib) + (u ? 2 * u - 1 : 0) >= w1) return;   // uniform per CTA

    // ---- initial loads ----
    int type = UNIT_TYPE(ib, u);
    int d0 = (u == 0) ? 0 : (2 * u - 1);
    int jA = (ib + d0) & 63;
    int jB = (ib + d0 + 1) & 63;
    cpasync_tile128(offA, g_Z + (size_t)ib * 128 * DIM, tid);
    if (type >= 1) cpasync_tile128(offB, g_Z + (size_t)jA * 128 * DIM, tid);
    if (type == 2) cpasync_tile128(offB + 128 * ROW_B, g_Z + (size_t)jB * 128 * DIM, tid);
    CP_COMMIT();
    if (tid < 256) {
        int j = (tid < 128) ? jA : jB;
        labs[tid] = g_lab[j * 128 + (tid & 127)];
    }
    int slot = 0;

    // ---- row state ----
    int lab_row[4], row_g[4];
    float pos[4], se[4];
#pragma unroll
    for (int s = 0; s < 4; s++) {
        row_g[s]   = ib * 128 + wm + (s >> 1) * 16 + g + 8 * (s & 1);
        lab_row[s] = g_lab[row_g[s]];
        pos[s] = 0.f;  se[s] = 0.f;
    }
    CP_WAIT0();
    __syncthreads();

    while (true) {
        // next unit
        int un = u + 1, ibn = ib;
        if (un > 16) { ibn++; un = 0; }
        bool has_next = (ibn < 64) && (unit_base(ibn) + (un ? 2 * un - 1 : 0)) < w1;
        int typen = 0, jAn = 0, jBn = 0;
        if (has_next) {
            int dn = (un == 0) ? 0 : (2 * un - 1);
            typen = UNIT_TYPE(ibn, un);
            jAn = (ibn + dn) & 63;
            jBn = (ibn + dn + 1) & 63;
        }
        const int* lb = labs + slot * 256;

        if (type == 2) {
            // ================= wide path: 128 x 256, warp tile 32x64 =================
            float c[2][8][4];
#pragma unroll
            for (int mt = 0; mt < 2; mt++)
#pragma unroll
                for (int nt = 0; nt < 8; nt++)
#pragma unroll
                    for (int i = 0; i < 4; i++) c[mt][nt][i] = 0.f;

#pragma unroll 4
            for (int kk = 0; kk < 16; kk++) {
                int kb = (kk * 16 + ((lane >> 4) << 3)) * 2;
                uint32_t a[2][4], b[4][4];
#pragma unroll
                for (int mt = 0; mt < 2; mt++) {
                    uint32_t addr = offA + (wm + mt * 16 + (lane & 15)) * ROW_B + kb;
                    LDSM_X4(a[mt][0], a[mt][1], a[mt][2], a[mt][3], addr);
                }
#pragma unroll
                for (int p = 0; p < 4; p++) {
                    uint32_t addr = offB + (wnW + p * 16 + (lane & 15)) * ROW_B + kb;
                    LDSM_X4(b[p][0], b[p][1], b[p][2], b[p][3], addr);
                }
#pragma unroll
                for (int mt = 0; mt < 2; mt++)
#pragma unroll
                    for (int nt = 0; nt < 8; nt++)
                        MMA16816(c[mt][nt], a[mt], b[nt >> 1][nt & 1], b[nt >> 1][2 + (nt & 1)]);
            }
            __syncthreads();   // all warps done reading A/B smem

            // prefetch next unit (overwrites A/B smem + labs slot^1; hidden behind epilogue)
            if (has_next) {
                if (ibn != ib) cpasync_tile128(offA, g_Z + (size_t)ibn * 128 * DIM, tid);
                if (typen >= 1) cpasync_tile128(offB, g_Z + (size_t)jAn * 128 * DIM, tid);
                if (typen == 2) cpasync_tile128(offB + 128 * ROW_B, g_Z + (size_t)jBn * 128 * DIM, tid);
                CP_COMMIT();
                if (tid < 256) {
                    int j = (tid < 128) ? jAn : jBn;
                    labs[(slot ^ 1) * 256 + tid] = g_lab[j * 128 + (tid & 127)];
                }
            }

            // dual epilogue, two n-halves to limit register pressure
#pragma unroll
            for (int h = 0; h < 2; h++) {
                float cpos[8], cse[8];
#pragma unroll
                for (int ci = 0; ci < 8; ci++) { cpos[ci] = 0.f; cse[ci] = 0.f; }
#pragma unroll
                for (int mt = 0; mt < 2; mt++)
#pragma unroll
                    for (int nt4 = 0; nt4 < 4; nt4++)
#pragma unroll
                        for (int i = 0; i < 4; i++) {
                            int nt  = h * 4 + nt4;
                            int s   = mt * 2 + (i >> 1);
                            int ci  = nt4 * 2 + (i & 1);
                            int col = wnW + nt * 8 + t4 * 2 + (i & 1);
                            float v = c[mt][nt][i];
                            if (lb[col] == lab_row[s]) {
                                pos[s] += v;  cpos[ci] += v;
                            } else {
                                float e = ex2f(v * K2);
                                se[s] += e;   cse[ci] += e;
                            }
                        }
#pragma unroll
                for (int ci = 0; ci < 8; ci++) {
                    float p = cpos[ci], e = cse[ci];
                    p += __shfl_xor_sync(0xffffffffu, p, 4);
                    p += __shfl_xor_sync(0xffffffffu, p, 8);
                    p += __shfl_xor_sync(0xffffffffu, p, 16);
                    e += __shfl_xor_sync(0xffffffffu, e, 4);
                    e += __shfl_xor_sync(0xffffffffu, e, 8);
                    e += __shfl_xor_sync(0xffffffffu, e, 16);
                    if (lane < 4) {
                        int col  = wnW + (h * 4 + (ci >> 1)) * 8 + lane * 2 + (ci & 1);
                        int grow = ((col >> 7) ? jB : jA) * 128 + (col & 127);
                        atomicAdd(&g_pos[grow], p * INV_T);
                        atomicAdd(&g_se[grow],  e);
                    }
                }
            }
        } else {
            // ================= narrow path: 128 x 128, warp tile 32x32 =================
            uint32_t bbuf = (type == 0) ? offA : offB;
            float c[2][4][4];
#pragma unroll
            for (int mt = 0; mt < 2; mt++)
#pragma unroll
                for (int nt = 0; nt < 4; nt++)
#pragma unroll
                    for (int i = 0; i < 4; i++) c[mt][nt][i] = 0.f;

#pragma unroll
            for (int kk = 0; kk < 16; kk++) {
                int kb = (kk * 16 + ((lane >> 4) << 3)) * 2;
                uint32_t a[2][4], b[2][4];
#pragma unroll
                for (int mt = 0; mt < 2; mt++) {
                    uint32_t addr = offA + (wm + mt * 16 + (lane & 15)) * ROW_B + kb;
                    LDSM_X4(a[mt][0], a[mt][1], a[mt][2], a[mt][3], addr);
                }
#pragma unroll
                for (int p = 0; p < 2; p++) {
                    uint32_t addr = bbuf + (wnN + p * 16 + (lane & 15)) * ROW_B + kb;
                    LDSM_X4(b[p][0], b[p][1], b[p][2], b[p][3], addr);
                }
#pragma unroll
                for (int mt = 0; mt < 2; mt++)
#pragma unroll
                    for (int nt = 0; nt < 4; nt++)
                        MMA16816(c[mt][nt], a[mt], b[nt >> 1][nt & 1], b[nt >> 1][2 + (nt & 1)]);
            }
            __syncthreads();

            if (has_next) {
                if (ibn != ib) cpasync_tile128(offA, g_Z + (size_t)ibn * 128 * DIM, tid);
                if (typen >= 1) cpasync_tile128(offB, g_Z + (size_t)jAn * 128 * DIM, tid);
                if (typen == 2) cpasync_tile128(offB + 128 * ROW_B, g_Z + (size_t)jBn * 128 * DIM, tid);
                CP_COMMIT();
                if (tid < 256) {
                    int j = (tid < 128) ? jAn : jBn;
                    labs[(slot ^ 1) * 256 + tid] = g_lab[j * 128 + (tid & 127)];
                }
            }

            if (type == 0) {
                // diagonal: row accumulation only, self excluded
#pragma unroll
                for (int mt = 0; mt < 2; mt++)
#pragma unroll
                    for (int nt = 0; nt < 4; nt++)
#pragma unroll
                        for (int i = 0; i < 4; i++) {
                            int s    = mt * 2 + (i >> 1);
                            int coll = wnN + nt * 8 + t4 * 2 + (i & 1);
                            float v  = c[mt][nt][i];
                            if (lb[coll] == lab_row[s]) {
                                if (ib * 128 + coll != row_g[s]) pos[s] += v;
                            } else {
                                se[s] += ex2f(v * K2);
                            }
                        }
            } else {
                // single off-diagonal: dual accumulation
                float cpos[8], cse[8];
#pragma unroll
                for (int ci = 0; ci < 8; ci++) { cpos[ci] = 0.f; cse[ci] = 0.f; }
#pragma unroll
                for (int mt = 0; mt < 2; mt++)
#pragma unroll
                    for (int nt = 0; nt < 4; nt++)
#pragma unroll
                        for (int i = 0; i < 4; i++) {
                            int s    = mt * 2 + (i >> 1);
                            int ci   = nt * 2 + (i & 1);
                            int coll = wnN + nt * 8 + t4 * 2 + (i & 1);
                            float v  = c[mt][nt][i];
                            if (lb[coll] == lab_row[s]) {
                                pos[s] += v;  cpos[ci] += v;
                            } else {
                                float e = ex2f(v * K2);
                                se[s] += e;   cse[ci] += e;
                            }
                        }
#pragma unroll
                for (int ci = 0; ci < 8; ci++) {
                    float p = cpos[ci], e = cse[ci];
                    p += __shfl_xor_sync(0xffffffffu, p, 4);
                    p += __shfl_xor_sync(0xffffffffu, p, 8);
                    p += __shfl_xor_sync(0xffffffffu, p, 16);
                    e += __shfl_xor_sync(0xffffffffu, e, 4);
                    e += __shfl_xor_sync(0xffffffffu, e, 8);
                    e += __shfl_xor_sync(0xffffffffu, e, 16);
                    if (lane < 4) {
                        int col = wnN + (ci >> 1) * 8 + lane * 2 + (ci & 1);
                        atomicAdd(&g_pos[jA * 128 + col], p * INV_T);
                        atomicAdd(&g_se[jA * 128 + col],  e);
                    }
                }
            }
        }

        // ib change: flush + reset row accumulators
        if (has_next && ibn != ib) {
#pragma unroll
            for (int s = 0; s < 4; s++) {
                float p = pos[s], e = se[s];
                p += __shfl_xor_sync(0xffffffffu, p, 1);
                p += __shfl_xor_sync(0xffffffffu, p, 2);
                e += __shfl_xor_sync(0xffffffffu, e, 1);
                e += __shfl_xor_sync(0xffffffffu, e, 2);
                if (t4 == 0) {
                    atomicAdd(&g_pos[row_g[s]], p * INV_T);
                    atomicAdd(&g_se[row_g[s]],  e);
                }
            }
#pragma unroll
            for (int s = 0; s < 4; s++) {
                row_g[s]   = ibn * 128 + wm + (s >> 1) * 16 + g + 8 * (s & 1);
                lab_row[s] = g_lab[row_g[s]];
                pos[s] = 0.f;  se[s] = 0.f;
            }
        }
        if (!has_next) break;
        CP_WAIT0();
        __syncthreads();
        ib = ibn; u = un; type = typen; jA = jAn; jB = jBn; slot ^= 1;
    }

    // final flush
#pragma unroll
    for (int s = 0; s < 4; s++) {
        float p = pos[s], e = se[s];
        p += __shfl_xor_sync(0xffffffffu, p, 1);
        p += __shfl_xor_sync(0xffffffffu, p, 2);
        e += __shfl_xor_sync(0xffffffffu, e, 1);
        e += __shfl_xor_sync(0xffffffffu, e, 2);
        if (t4 == 0) {
            atomicAdd(&g_pos[row_g[s]], p * INV_T);
            atomicAdd(&g_se[row_g[s]],  e);
        }
    }
}

// ============================ kernel 3: final reduction (32 CTAs x 256) ============================
__global__ void k_final(float* __restrict__ out) {
    __shared__ float red[8];
    int r = blockIdx.x * 256 + threadIdx.x;
    // loss_i = logaddexp(0, lse_neg - pos_sim); |sim|<=14.3 so sum-exp is fp32-safe
    float x  = logf(g_se[r]) - g_pos[r];
    float li = (x > 0.f) ? (x + log1pf(expf(-x))) : log1pf(expf(x));
#pragma unroll
    for (int o = 16; o > 0; o >>= 1) li += __shfl_xor_sync(0xffffffffu, li, o);
    if ((threadIdx.x & 31) == 0) red[threadIdx.x >> 5] = li;
    __syncthreads();
    if (threadIdx.x < 32) {
        float a = (threadIdx.x < 8) ? red[threadIdx.x] : 0.f;
#pragma unroll
        for (int o = 4; o > 0; o >>= 1) a += __shfl_xor_sync(0xffffffffu, a, o);
        if (threadIdx.x == 0) atomicAdd(out, a * (1.0f / (float)NROWS));
    }
}

// ============================ launch ============================
extern "C" void kernel_launch(void* const* d_in, const int* in_sizes, int n_in,
                              void* d_out, int out_size) {
    (void)in_sizes; (void)n_in; (void)out_size;
    const float* zi  = (const float*)d_in[0];
    const float* zj  = (const float*)d_in[1];
    const int*   lab = (const int*)d_in[2];    // int32 or int64; auto-detected

    cudaFuncSetAttribute(k_sim, cudaFuncAttributeMaxDynamicSharedMemorySize, SMEM_BYTES);

    k_norm<<<NROWS / 8, 256>>>(zi, zj, lab, (float*)d_out);
    k_sim<<<NCTA, 512, SMEM_BYTES>>>();
    k_final<<<NROWS / 256, 256>>>((float*)d_out);
}

// round 7
// speedup vs baseline: 1.0900x; 1.0900x over previous
#include <cuda_runtime.h>
#include <cuda_fp16.h>
#include <cstdint>

// ============================ problem constants ============================
#define NROWS   8192
#define BHALF   4096
#define DIM     256
#define TM      128
#define TN      128
#define INV_T   14.2857142857142857f      // 1/0.07
#define K2      20.609929155556620f       // log2(e)/0.07  (for ex2)

#define NCTA    148
#define NTILES  2080        // circulant upper triangle of 64x64 blocks

// SMEM tile: 128 rows x (256 fp16 + 8 pad) = 528 B/row -> conflict-free ldmatrix
#define ROW_B   528
#define TILEB   (128 * ROW_B)      // 67584
#define OFF_A   1024               // labs[2][128] ints live at offset 0
#define OFF_B0  (OFF_A + TILEB)    // 68608
#define OFF_B1  (OFF_B0 + TILEB)   // 136192
#define SMEM_BYTES (OFF_B1 + TILEB) // 203776

// ============================ device scratch ============================
__device__ __half g_Z[NROWS * DIM];    // normalized rows, fp16
__device__ int   g_lab[NROWS];
__device__ float g_pos[NROWS];
__device__ float g_se[NROWS];

// ============================ PTX helpers (baseline features only) ============================
__device__ __forceinline__ uint32_t smem_to_u32(const void* p) {
    uint32_t a;
    asm("{ .reg .u64 t; cvta.to.shared.u64 t, %1; cvt.u32.u64 %0, t; }" : "=r"(a) : "l"(p));
    return a;
}
__device__ __forceinline__ float ex2f(float x) {
    float y; asm("ex2.approx.f32 %0, %1;" : "=f"(y) : "f"(x)); return y;
}

#define LDSM_X4(r0, r1, r2, r3, addr) \
    asm volatile("ldmatrix.sync.aligned.m8n8.x4.shared.b16 {%0,%1,%2,%3}, [%4];" \
        : "=r"(r0), "=r"(r1), "=r"(r2), "=r"(r3) : "r"(addr))

// f16 accumulators: D/C are 2 x .f16x2 registers
#define MMA16816F16(c, a, b0, b1) \
    asm volatile("mma.sync.aligned.m16n8k16.row.col.f16.f16.f16.f16 " \
        "{%0,%1}, {%2,%3,%4,%5}, {%6,%7}, {%0,%1};" \
        : "+r"((c)[0]), "+r"((c)[1]) \
        : "r"((a)[0]), "r"((a)[1]), "r"((a)[2]), "r"((a)[3]), "r"(b0), "r"(b1))

#define CP_ASYNC16(dst_u32, src_ptr) \
    asm volatile("cp.async.cg.shared.global [%0], [%1], 16;" :: "r"(dst_u32), "l"(src_ptr))
#define CP_COMMIT() asm volatile("cp.async.commit_group;" ::: "memory")
#define CP_WAIT0()  asm volatile("cp.async.wait_group 0;" ::: "memory")

// tile t -> (ib, d); jb = (ib + d) & 63. ib<32 has d=0..32 (33 tiles), ib>=32 has d=0..31.
__device__ __forceinline__ void decode_tile(int t, int& ib, int& d) {
    if (t < 32 * 33) { ib = t / 33; d = t - ib * 33; }
    else { int u = t - 32 * 33; ib = 32 + (u >> 5); d = u & 31; }
}

// ============================ kernel 1: normalize + fp16 + labels + init ============================
__global__ void k_norm(const float* __restrict__ zi, const float* __restrict__ zj,
                       const int* __restrict__ lab32, float* __restrict__ out) {
    __shared__ int stride_sh;
    if (threadIdx.x == 0) {
        int ored = 0;
#pragma unroll
        for (int i = 0; i < 32; i++) ored |= lab32[2 * i + 1];
        stride_sh = (ored == 0) ? 2 : 1;   // int64 storage has all-zero odd words (labels < 1000)
        if (blockIdx.x == 0) out[0] = 0.f;
    }
    int row  = blockIdx.x * 8 + (threadIdx.x >> 5);
    int lane = threadIdx.x & 31;
    const float* src = (row < BHALF) ? (zi + (size_t)row * DIM)
                                     : (zj + (size_t)(row - BHALF) * DIM);
    float v[8];
    float ss = 0.f;
#pragma unroll
    for (int i = 0; i < 8; i++) { v[i] = src[i * 32 + lane]; ss += v[i] * v[i]; }
#pragma unroll
    for (int o = 16; o > 0; o >>= 1) ss += __shfl_xor_sync(0xffffffffu, ss, o);
    float inv = 1.f / fmaxf(sqrtf(ss), 1e-12f);
    __half* dst = g_Z + (size_t)row * DIM;
#pragma unroll
    for (int i = 0; i < 8; i++) dst[i * 32 + lane] = __float2half(v[i] * inv);
    __syncthreads();
    if (lane == 0) {
        g_lab[row] = lab32[(row & (BHALF - 1)) * stride_sh];
        g_pos[row] = 0.f;
        g_se[row]  = 0.f;
    }
}

// ============================ kernel 2: symmetric GEMM, persistent balanced CTAs ============================
__device__ __forceinline__ void cpasync_tile(uint32_t dst, const __half* src, int tid) {
#pragma unroll
    for (int it = 0; it < 8; it++) {
        int idx = tid + it * 512;        // 0..4095 16B-chunks
        int row = idx >> 5, c = idx & 31;
        const char* s = reinterpret_cast<const char*>(src) + row * 512 + c * 16;
        CP_ASYNC16(dst + row * ROW_B + c * 16, s);
    }
}

__global__ void __launch_bounds__(512, 1) k_sim() {
    extern __shared__ char smem[];
    uint32_t su = smem_to_u32(smem);
    int* labs = reinterpret_cast<int*>(smem);     // [2][128]

    int tid  = threadIdx.x;
    int lane = tid & 31;
    int wid  = tid >> 5;                 // 0..15
    const int wm = (wid >> 2) * 32;      // warp m-offset (4 bands of 32 rows)
    const int wn = (wid & 3) * 32;       // warp n-offset (4 bands of 32 cols)
    const int g  = lane >> 2;
    const int t4 = lane & 3;

    int cta = blockIdx.x;
    int t0 = (cta * NTILES) / NCTA;
    int t1 = ((cta + 1) * NTILES) / NCTA;

    // pre-loop: prefetch first tile's B + labels into buffer 0
    {
        int ib0, d0; decode_tile(t0, ib0, d0);
        int jb0 = (ib0 + d0) & 63;
        if (d0 != 0) cpasync_tile(su + OFF_B0, g_Z + (size_t)jb0 * TN * DIM, tid);
        CP_COMMIT();
        if (tid < 128) labs[tid] = g_lab[jb0 * TN + tid];
    }

    int cur_ib = -1;
    int lab_row[4], row_g[4];
    float pos[4], se[4];

    for (int t = t0; t < t1; t++) {
        int ib, d; decode_tile(t, ib, d);
        int jb  = (ib + d) & 63;
        int buf = (t - t0) & 1;

        if (ib != cur_ib) {
            // flush row accumulators of the previous ib
            if (cur_ib >= 0) {
#pragma unroll
                for (int s = 0; s < 4; s++) {
                    float p = pos[s], e = se[s];
                    p += __shfl_xor_sync(0xffffffffu, p, 1);
                    p += __shfl_xor_sync(0xffffffffu, p, 2);
                    e += __shfl_xor_sync(0xffffffffu, e, 1);
                    e += __shfl_xor_sync(0xffffffffu, e, 2);
                    if (t4 == 0) {
                        atomicAdd(&g_pos[row_g[s]], p * INV_T);
                        atomicAdd(&g_se[row_g[s]],  e);
                    }
                }
            }
            cpasync_tile(su + OFF_A, g_Z + (size_t)ib * TM * DIM, tid);
            CP_COMMIT();
            CP_WAIT0();            // also drains any in-flight B prefetch
            __syncthreads();
            cur_ib = ib;
#pragma unroll
            for (int s = 0; s < 4; s++) {
                int mt = s >> 1, h = s & 1;
                row_g[s]   = ib * TM + wm + mt * 16 + g + 8 * h;
                lab_row[s] = g_lab[row_g[s]];
                pos[s] = 0.f;  se[s] = 0.f;
            }
        }

        uint32_t bbuf = (d == 0) ? (su + OFF_A) : (su + (buf ? OFF_B1 : OFF_B0));

        // prefetch next tile's B + labels
        if (t + 1 < t1) {
            int ibn, dn; decode_tile(t + 1, ibn, dn);
            int jn = (ibn + dn) & 63;
            if (dn != 0) cpasync_tile(su + ((buf ^ 1) ? OFF_B1 : OFF_B0),
                                      g_Z + (size_t)jn * TN * DIM, tid);
            CP_COMMIT();
            if (tid < 128) labs[(buf ^ 1) * 128 + tid] = g_lab[jn * TN + tid];
        }

        // ---- GEMM: warp computes 32x32, K=256, f16 accumulate ----
        uint32_t c[2][4][2];
#pragma unroll
        for (int mt = 0; mt < 2; mt++)
#pragma unroll
            for (int nt = 0; nt < 4; nt++) { c[mt][nt][0] = 0u; c[mt][nt][1] = 0u; }

#pragma unroll
        for (int kk = 0; kk < 16; kk++) {
            int kb = (kk * 16 + ((lane >> 4) << 3)) * 2;   // byte offset in row
            uint32_t a[2][4], b[2][4];
#pragma unroll
            for (int mt = 0; mt < 2; mt++) {
                uint32_t addr = su + OFF_A + (wm + mt * 16 + (lane & 15)) * ROW_B + kb;
                LDSM_X4(a[mt][0], a[mt][1], a[mt][2], a[mt][3], addr);
            }
#pragma unroll
            for (int p = 0; p < 2; p++) {
                uint32_t addr = bbuf + (wn + p * 16 + (lane & 15)) * ROW_B + kb;
                LDSM_X4(b[p][0], b[p][1], b[p][2], b[p][3], addr);
            }
#pragma unroll
            for (int mt = 0; mt < 2; mt++)
#pragma unroll
                for (int nt = 0; nt < 4; nt++)
                    MMA16816F16(c[mt][nt], a[mt], b[nt >> 1][nt & 1], b[nt >> 1][2 + (nt & 1)]);
        }

        // ---- fused epilogue (unpack f16x2 -> float) ----
        const int* lb = labs + buf * 128;
        if (d == 0) {
            // diagonal tile: row accumulation only, with self exclusion
#pragma unroll
            for (int mt = 0; mt < 2; mt++)
#pragma unroll
                for (int nt = 0; nt < 4; nt++)
#pragma unroll
                    for (int j = 0; j < 2; j++) {
                        int s = mt * 2 + j;
                        float2 f = __half22float2(*reinterpret_cast<__half2*>(&c[mt][nt][j]));
#pragma unroll
                        for (int q = 0; q < 2; q++) {
                            int coll = wn + nt * 8 + t4 * 2 + q;
                            float v  = q ? f.y : f.x;
                            if (lb[coll] == lab_row[s]) {
                                if (jb * TN + coll != row_g[s]) pos[s] += v;
                            } else {
                                se[s] += ex2f(v * K2);
                            }
                        }
                    }
        } else {
            // off-diagonal: dual accumulation (rows of block ib, mirrored rows of block jb)
            float cpos[8], cse[8];
#pragma unroll
            for (int ci = 0; ci < 8; ci++) { cpos[ci] = 0.f; cse[ci] = 0.f; }
#pragma unroll
            for (int mt = 0; mt < 2; mt++)
#pragma unroll
                for (int nt = 0; nt < 4; nt++)
#pragma unroll
                    for (int j = 0; j < 2; j++) {
                        int s = mt * 2 + j;
                        float2 f = __half22float2(*reinterpret_cast<__half2*>(&c[mt][nt][j]));
#pragma unroll
                        for (int q = 0; q < 2; q++) {
                            int ci   = nt * 2 + q;
                            int coll = wn + nt * 8 + t4 * 2 + q;
                            float v  = q ? f.y : f.x;
                            if (lb[coll] == lab_row[s]) {
                                pos[s] += v;  cpos[ci] += v;
                            } else {
                                float e = ex2f(v * K2);
                                se[s] += e;   cse[ci] += e;
                            }
                        }
                    }
            // reduce col partials across the 8 row-groups (g), flush with atomics
#pragma unroll
            for (int ci = 0; ci < 8; ci++) {
                float p = cpos[ci], e = cse[ci];
                p += __shfl_xor_sync(0xffffffffu, p, 4);
                p += __shfl_xor_sync(0xffffffffu, p, 8);
                p += __shfl_xor_sync(0xffffffffu, p, 16);
                e += __shfl_xor_sync(0xffffffffu, e, 4);
                e += __shfl_xor_sync(0xffffffffu, e, 8);
                e += __shfl_xor_sync(0xffffffffu, e, 16);
                if (lane < 4) {
                    int col = wn + (ci >> 1) * 8 + lane * 2 + (ci & 1);
                    atomicAdd(&g_pos[jb * TN + col], p * INV_T);
                    atomicAdd(&g_se[jb * TN + col],  e);
                }
            }
        }

        CP_WAIT0();
        __syncthreads();
    }

    // final flush of row accumulators
    if (cur_ib >= 0) {
#pragma unroll
        for (int s = 0; s < 4; s++) {
            float p = pos[s], e = se[s];
            p += __shfl_xor_sync(0xffffffffu, p, 1);
            p += __shfl_xor_sync(0xffffffffu, p, 2);
            e += __shfl_xor_sync(0xffffffffu, e, 1);
            e += __shfl_xor_sync(0xffffffffu, e, 2);
            if (t4 == 0) {
                atomicAdd(&g_pos[row_g[s]], p * INV_T);
                atomicAdd(&g_se[row_g[s]],  e);
            }
        }
    }
}

// ============================ kernel 3: final reduction (32 CTAs x 256) ============================
__global__ void k_final(float* __restrict__ out) {
    __shared__ float red[8];
    int r = blockIdx.x * 256 + threadIdx.x;
    // loss_i = logaddexp(0, lse_neg - pos_sim); |sim|<=14.3 so sum-exp is fp32-safe
    float x  = logf(g_se[r]) - g_pos[r];
    float li = (x > 0.f) ? (x + log1pf(expf(-x))) : log1pf(expf(x));
#pragma unroll
    for (int o = 16; o > 0; o >>= 1) li += __shfl_xor_sync(0xffffffffu, li, o);
    if ((threadIdx.x & 31) == 0) red[threadIdx.x >> 5] = li;
    __syncthreads();
    if (threadIdx.x < 32) {
        float a = (threadIdx.x < 8) ? red[threadIdx.x] : 0.f;
#pragma unroll
        for (int o = 4; o > 0; o >>= 1) a += __shfl_xor_sync(0xffffffffu, a, o);
        if (threadIdx.x == 0) atomicAdd(out, a * (1.0f / (float)NROWS));
    }
}

// ============================ launch ============================
extern "C" void kernel_launch(void* const* d_in, const int* in_sizes, int n_in,
                              void* d_out, int out_size) {
    (void)in_sizes; (void)n_in; (void)out_size;
    const float* zi  = (const float*)d_in[0];
    const float* zj  = (const float*)d_in[1];
    const int*   lab = (const int*)d_in[2];    // int32 or int64; auto-detected

    cudaFuncSetAttribute(k_sim, cudaFuncAttributeMaxDynamicSharedMemorySize, SMEM_BYTES);

    k_norm<<<NROWS / 8, 256>>>(zi, zj, lab, (float*)d_out);
    k_sim<<<NCTA, 512, SMEM_BYTES>>>();
    k_final<<<NROWS / 256, 256>>>((float*)d_out);
}

// round 8
// speedup vs baseline: 1.1538x; 1.0586x over previous
#include <cuda_runtime.h>
#include <cuda_fp16.h>
#include <cstdint>

// ============================ problem constants ============================
#define NROWS   8192
#define BHALF   4096
#define DIM     256
#define TM      128
#define TN      128
#define INV_T   14.2857142857142857f      // 1/0.07
#define K2      20.609929155556620f       // log2(e)/0.07  (for ex2)

#define NCTA    148
#define NTILES  2080        // circulant upper triangle of 64x64 blocks

// SMEM tile: 128 rows x (256 fp16 + 8 pad) = 528 B/row -> conflict-free ldmatrix
#define ROW_B   528
#define TILEB   (128 * ROW_B)      // 67584
#define OFF_A   1024               // labs[2][128] ints live at offset 0
#define OFF_B0  (OFF_A + TILEB)    // 68608
#define OFF_B1  (OFF_B0 + TILEB)   // 136192
#define SMEM_BYTES (OFF_B1 + TILEB) // 203776

// ============================ device scratch ============================
__device__ __half g_Z[NROWS * DIM];    // normalized rows, fp16
__device__ int   g_lab[NROWS];
__device__ float g_pos[NROWS];
__device__ float g_se[NROWS];

// ============================ PTX helpers (baseline features only) ============================
__device__ __forceinline__ uint32_t smem_to_u32(const void* p) {
    uint32_t a;
    asm("{ .reg .u64 t; cvta.to.shared.u64 t, %1; cvt.u32.u64 %0, t; }" : "=r"(a) : "l"(p));
    return a;
}
__device__ __forceinline__ float ex2f(float x) {
    float y; asm("ex2.approx.f32 %0, %1;" : "=f"(y) : "f"(x)); return y;
}

#define LDSM_X4(r0, r1, r2, r3, addr) \
    asm volatile("ldmatrix.sync.aligned.m8n8.x4.shared.b16 {%0,%1,%2,%3}, [%4];" \
        : "=r"(r0), "=r"(r1), "=r"(r2), "=r"(r3) : "r"(addr))

#define MMA16816(c, a, b0, b1) \
    asm volatile("mma.sync.aligned.m16n8k16.row.col.f32.f16.f16.f32 " \
        "{%0,%1,%2,%3}, {%4,%5,%6,%7}, {%8,%9}, {%0,%1,%2,%3};" \
        : "+f"((c)[0]), "+f"((c)[1]), "+f"((c)[2]), "+f"((c)[3]) \
        : "r"((a)[0]), "r"((a)[1]), "r"((a)[2]), "r"((a)[3]), "r"(b0), "r"(b1))

#define CP_ASYNC16(dst_u32, src_ptr) \
    asm volatile("cp.async.cg.shared.global [%0], [%1], 16;" :: "r"(dst_u32), "l"(src_ptr))
#define CP_COMMIT() asm volatile("cp.async.commit_group;" ::: "memory")
#define CP_WAIT0()  asm volatile("cp.async.wait_group 0;" ::: "memory")

// tile t -> (ib, d); jb = (ib + d) & 63. ib<32 has d=0..32 (33 tiles), ib>=32 has d=0..31.
__device__ __forceinline__ void decode_tile(int t, int& ib, int& d) {
    if (t < 32 * 33) { ib = t / 33; d = t - ib * 33; }
    else { int u = t - 32 * 33; ib = 32 + (u >> 5); d = u & 31; }
}

// ============================ kernel 1: normalize + fp16 + labels + init ============================
__global__ void k_norm(const float* __restrict__ zi, const float* __restrict__ zj,
                       const int* __restrict__ lab32, float* __restrict__ out) {
    __shared__ int stride_sh;
    if (threadIdx.x == 0) {
        int ored = 0;
#pragma unroll
        for (int i = 0; i < 32; i++) ored |= lab32[2 * i + 1];
        stride_sh = (ored == 0) ? 2 : 1;   // int64 storage has all-zero odd words (labels < 1000)
        if (blockIdx.x == 0) out[0] = 0.f;
    }
    int row  = blockIdx.x * 8 + (threadIdx.x >> 5);
    int lane = threadIdx.x & 31;
    const float* src = (row < BHALF) ? (zi + (size_t)row * DIM)
                                     : (zj + (size_t)(row - BHALF) * DIM);
    float v[8];
    float ss = 0.f;
#pragma unroll
    for (int i = 0; i < 8; i++) { v[i] = src[i * 32 + lane]; ss += v[i] * v[i]; }
#pragma unroll
    for (int o = 16; o > 0; o >>= 1) ss += __shfl_xor_sync(0xffffffffu, ss, o);
    float inv = 1.f / fmaxf(sqrtf(ss), 1e-12f);
    __half* dst = g_Z + (size_t)row * DIM;
#pragma unroll
    for (int i = 0; i < 8; i++) dst[i * 32 + lane] = __float2half(v[i] * inv);
    __syncthreads();
    if (lane == 0) {
        g_lab[row] = lab32[(row & (BHALF - 1)) * stride_sh];
        g_pos[row] = 0.f;
        g_se[row]  = 0.f;
    }
}

// ============================ kernel 2: pipelined symmetric GEMM ============================
__device__ __forceinline__ void cpasync_tile(uint32_t dst, const __half* src, int tid) {
#pragma unroll
    for (int it = 0; it < 8; it++) {
        int idx = tid + it * 512;        // 0..4095 16B-chunks
        int row = idx >> 5, c = idx & 31;
        const char* s = reinterpret_cast<const char*>(src) + row * 512 + c * 16;
        CP_ASYNC16(dst + row * ROW_B + c * 16, s);
    }
}

// Column-group epilogue for the PREVIOUS off-diagonal tile:
// 4 c-values + row accumulate + col reduce (shfl over g) + mirrored-row atomics.
__device__ __forceinline__ void epi_group(
    int ci, const float cprev[2][4][4], const int labreg[8], const int lab_row[4],
    float pos[4], float se[4], int jb_prev, int wn, int lane)
{
    int nt = ci >> 1, q = ci & 1;
    float cp = 0.f, ce = 0.f;
#pragma unroll
    for (int mt = 0; mt < 2; mt++)
#pragma unroll
        for (int h = 0; h < 2; h++) {
            int s = mt * 2 + h;
            float v = cprev[mt][nt][h * 2 + q];
            if (labreg[ci] == lab_row[s]) { pos[s] += v; cp += v; }
            else { float e = ex2f(v * K2); se[s] += e; ce += e; }
        }
    cp += __shfl_xor_sync(0xffffffffu, cp, 4);
    cp += __shfl_xor_sync(0xffffffffu, cp, 8);
    cp += __shfl_xor_sync(0xffffffffu, cp, 16);
    ce += __shfl_xor_sync(0xffffffffu, ce, 4);
    ce += __shfl_xor_sync(0xffffffffu, ce, 8);
    ce += __shfl_xor_sync(0xffffffffu, ce, 16);
    if (lane < 4) {
        int col = wn + nt * 8 + lane * 2 + q;
        atomicAdd(&g_pos[jb_prev * TN + col], cp * INV_T);
        atomicAdd(&g_se[jb_prev * TN + col],  ce);
    }
}

// GEMM for the current tile, optionally interleaving the previous tile's epilogue
// (one ci-group per odd kk) so MUFU/FMA/SHFL overlap with tensor/LDSM.
template <bool FUSE>
__device__ __forceinline__ void gemm_tile(
    uint32_t aBase, uint32_t bBase, int lane,
    float c[2][4][4],
    const float cprev[2][4][4], const int labreg[8], const int lab_row[4],
    float pos[4], float se[4], int jb_prev, int wn)
{
#pragma unroll
    for (int mt = 0; mt < 2; mt++)
#pragma unroll
        for (int nt = 0; nt < 4; nt++)
#pragma unroll
            for (int i = 0; i < 4; i++) c[mt][nt][i] = 0.f;

#pragma unroll
    for (int kk = 0; kk < 16; kk++) {
        int kb = (kk * 16 + ((lane >> 4) << 3)) * 2;   // byte offset in row
        uint32_t a[2][4], b[2][4];
#pragma unroll
        for (int mt = 0; mt < 2; mt++) {
            uint32_t addr = aBase + (mt * 16 + (lane & 15)) * ROW_B + kb;
            LDSM_X4(a[mt][0], a[mt][1], a[mt][2], a[mt][3], addr);
        }
#pragma unroll
        for (int p = 0; p < 2; p++) {
            uint32_t addr = bBase + (p * 16 + (lane & 15)) * ROW_B + kb;
            LDSM_X4(b[p][0], b[p][1], b[p][2], b[p][3], addr);
        }
#pragma unroll
        for (int mt = 0; mt < 2; mt++)
#pragma unroll
            for (int nt = 0; nt < 4; nt++)
                MMA16816(c[mt][nt], a[mt], b[nt >> 1][nt & 1], b[nt >> 1][2 + (nt & 1)]);

        if (FUSE && (kk & 1))
            epi_group(kk >> 1, cprev, labreg, lab_row, pos, se, jb_prev, wn, lane);
    }
}

__global__ void __launch_bounds__(512, 1) k_sim() {
    extern __shared__ char smem[];
    uint32_t su = smem_to_u32(smem);
    int* labs = reinterpret_cast<int*>(smem);     // [2][128]

    int tid  = threadIdx.x;
    int lane = tid & 31;
    int wid  = tid >> 5;                 // 0..15
    const int wm = (wid >> 2) * 32;      // warp m-offset (4 bands of 32 rows)
    const int wn = (wid & 3) * 32;       // warp n-offset (4 bands of 32 cols)
    const int g  = lane >> 2;
    const int t4 = lane & 3;

    int cta = blockIdx.x;
    int t0 = (cta * NTILES) / NCTA;
    int t1 = ((cta + 1) * NTILES) / NCTA;

    // pre-loop: prefetch first tile's B + labels into buffer 0
    {
        int ib0, d0; decode_tile(t0, ib0, d0);
        int jb0 = (ib0 + d0) & 63;
        if (d0 != 0) cpasync_tile(su + OFF_B0, g_Z + (size_t)jb0 * TN * DIM, tid);
        CP_COMMIT();
        if (tid < 128) labs[tid] = g_lab[jb0 * TN + tid];
    }

    int cur_ib = -1;
    int lab_row[4], row_g[4];
    float pos[4], se[4];

    // pipeline state: pending off-diagonal epilogue of the previous tile
    bool  pending = false;
    float cprev[2][4][4];
    int   labreg[8];
    int   jb_prev = 0;

    float c[2][4][4];

    for (int t = t0; t < t1; t++) {
        int ib, d; decode_tile(t, ib, d);
        int jb  = (ib + d) & 63;
        int buf = (t - t0) & 1;

        if (ib != cur_ib) {
            // drain the pipeline, then flush row accumulators of the previous ib
            if (pending) {
#pragma unroll
                for (int ci = 0; ci < 8; ci++)
                    epi_group(ci, cprev, labreg, lab_row, pos, se, jb_prev, wn, lane);
                pending = false;
            }
            if (cur_ib >= 0) {
#pragma unroll
                for (int s = 0; s < 4; s++) {
                    float p = pos[s], e = se[s];
                    p += __shfl_xor_sync(0xffffffffu, p, 1);
                    p += __shfl_xor_sync(0xffffffffu, p, 2);
                    e += __shfl_xor_sync(0xffffffffu, e, 1);
                    e += __shfl_xor_sync(0xffffffffu, e, 2);
                    if (t4 == 0) {
                        atomicAdd(&g_pos[row_g[s]], p * INV_T);
                        atomicAdd(&g_se[row_g[s]],  e);
                    }
                }
            }
            cpasync_tile(su + OFF_A, g_Z + (size_t)ib * TM * DIM, tid);
            CP_COMMIT();
            CP_WAIT0();            // also drains any in-flight B prefetch
            __syncthreads();
            cur_ib = ib;
#pragma unroll
            for (int s = 0; s < 4; s++) {
                int mt = s >> 1, h = s & 1;
                row_g[s]   = ib * TM + wm + mt * 16 + g + 8 * h;
                lab_row[s] = g_lab[row_g[s]];
                pos[s] = 0.f;  se[s] = 0.f;
            }
        }

        uint32_t bbuf = (d == 0) ? (su + OFF_A) : (su + (buf ? OFF_B1 : OFF_B0));

        // prefetch next tile's B + labels
        if (t + 1 < t1) {
            int ibn, dn; decode_tile(t + 1, ibn, dn);
            int jn = (ibn + dn) & 63;
            if (dn != 0) cpasync_tile(su + ((buf ^ 1) ? OFF_B1 : OFF_B0),
                                      g_Z + (size_t)jn * TN * DIM, tid);
            CP_COMMIT();
            if (tid < 128) labs[(buf ^ 1) * 128 + tid] = g_lab[jn * TN + tid];
        }

        uint32_t aBase = su + OFF_A + wm * ROW_B;
        uint32_t bBase = bbuf + wn * ROW_B;
        const int* lb  = labs + buf * 128;

        if (d == 0) {
            // diagonal tile (always right after ib change -> pipeline is empty):
            // GEMM + standalone row-only epilogue with self-exclusion.
            gemm_tile<false>(aBase, bBase, lane, c, cprev, labreg, lab_row, pos, se, jb_prev, wn);
#pragma unroll
            for (int mt = 0; mt < 2; mt++)
#pragma unroll
                for (int nt = 0; nt < 4; nt++)
#pragma unroll
                    for (int i = 0; i < 4; i++) {
                        int s    = mt * 2 + (i >> 1);
                        int coll = wn + nt * 8 + t4 * 2 + (i & 1);
                        float v  = c[mt][nt][i];
                        if (lb[coll] == lab_row[s]) {
                            if (ib * TM + coll != row_g[s]) pos[s] += v;
                        } else {
                            se[s] += ex2f(v * K2);
                        }
                    }
        } else {
            // off-diagonal tile: GEMM fused with the previous tile's epilogue
            if (pending)
                gemm_tile<true>(aBase, bBase, lane, c, cprev, labreg, lab_row, pos, se, jb_prev, wn);
            else
                gemm_tile<false>(aBase, bBase, lane, c, cprev, labreg, lab_row, pos, se, jb_prev, wn);

            // register the just-computed tile as pending: snapshot labels + c
#pragma unroll
            for (int ci = 0; ci < 8; ci++)
                labreg[ci] = lb[wn + (ci >> 1) * 8 + t4 * 2 + (ci & 1)];
#pragma unroll
            for (int mt = 0; mt < 2; mt++)
#pragma unroll
                for (int nt = 0; nt < 4; nt++)
#pragma unroll
                    for (int i = 0; i < 4; i++) cprev[mt][nt][i] = c[mt][nt][i];
            jb_prev = jb;
            pending = true;
        }

        CP_WAIT0();
        __syncthreads();
    }

    // drain pipeline + final row flush
    if (pending) {
#pragma unroll
        for (int ci = 0; ci < 8; ci++)
            epi_group(ci, cprev, labreg, lab_row, pos, se, jb_prev, wn, lane);
    }
    if (cur_ib >= 0) {
#pragma unroll
        for (int s = 0; s < 4; s++) {
            float p = pos[s], e = se[s];
            p += __shfl_xor_sync(0xffffffffu, p, 1);
            p += __shfl_xor_sync(0xffffffffu, p, 2);
            e += __shfl_xor_sync(0xffffffffu, e, 1);
            e += __shfl_xor_sync(0xffffffffu, e, 2);
            if (t4 == 0) {
                atomicAdd(&g_pos[row_g[s]], p * INV_T);
                atomicAdd(&g_se[row_g[s]],  e);
            }
        }
    }
}

// ============================ kernel 3: final reduction (32 CTAs x 256) ============================
__global__ void k_final(float* __restrict__ out) {
    __shared__ float red[8];
    int r = blockIdx.x * 256 + threadIdx.x;
    // loss_i = logaddexp(0, lse_neg - pos_sim); |sim|<=14.3 so sum-exp is fp32-safe
    float x  = logf(g_se[r]) - g_pos[r];
    float li = (x > 0.f) ? (x + log1pf(expf(-x))) : log1pf(expf(x));
#pragma unroll
    for (int o = 16; o > 0; o >>= 1) li += __shfl_xor_sync(0xffffffffu, li, o);
    if ((threadIdx.x & 31) == 0) red[threadIdx.x >> 5] = li;
    __syncthreads();
    if (threadIdx.x < 32) {
        float a = (threadIdx.x < 8) ? red[threadIdx.x] : 0.f;
#pragma unroll
        for (int o = 4; o > 0; o >>= 1) a += __shfl_xor_sync(0xffffffffu, a, o);
        if (threadIdx.x == 0) atomicAdd(out, a * (1.0f / (float)NROWS));
    }
}

// ============================ launch ============================
extern "C" void kernel_launch(void* const* d_in, const int* in_sizes, int n_in,
                              void* d_out, int out_size) {
    (void)in_sizes; (void)n_in; (void)out_size;
    const float* zi  = (const float*)d_in[0];
    const float* zj  = (const float*)d_in[1];
    const int*   lab = (const int*)d_in[2];    // int32 or int64; auto-detected

    cudaFuncSetAttribute(k_sim, cudaFuncAttributeMaxDynamicSharedMemorySize, SMEM_BYTES);

    k_norm<<<NROWS / 8, 256>>>(zi, zj, lab, (float*)d_out);
    k_sim<<<NCTA, 512, SMEM_BYTES>>>();
    k_final<<<NROWS / 256, 256>>>((float*)d_out);
}